// round 5
// baseline (speedup 1.0000x reference)
#include <cuda_runtime.h>

// Global accumulators (no allocation allowed — __device__ globals are the
// sanctioned scratch). Zeroed by a prologue kernel on every launch so the
// graph replays deterministically.
__device__ double g_inter;       // sum(actual * desire)
__device__ double g_desire_sum;  // sum(desire)
__device__ unsigned long long g_count;  // sum(actual) — exact integer

__global__ void fra_zero_kernel() {
    g_inter = 0.0;
    g_desire_sum = 0.0;
    g_count = 0ull;
}

// Warp-per-row: 32 lanes x float4 = 128 floats = one row of each input.
// Two coalesced 512B transactions per warp per row. Persistent grid-stride
// over rows; unrolled for MLP.
__global__ __launch_bounds__(256, 8)
void fra_main_kernel(const float4* __restrict__ o1,
                     const float4* __restrict__ o2,
                     const float*  __restrict__ desire,
                     int n_rows) {
    const int lane          = threadIdx.x & 31;
    const int warp_in_block = threadIdx.x >> 5;
    const int warps_per_blk = blockDim.x >> 5;
    const int warp_global   = blockIdx.x * warps_per_blk + warp_in_block;
    const int total_warps   = gridDim.x * warps_per_blk;

    double       l_inter = 0.0;
    double       l_des   = 0.0;
    unsigned int l_cnt   = 0u;

    const float margin_sq = 0.390625f;  // (1.25/2)^2

    #pragma unroll 4
    for (int row = warp_global; row < n_rows; row += total_warps) {
        const long base = (long)row * 32 + lane;
        const float4 a = o1[base];
        const float4 b = o2[base];
        const float dx = a.x - b.x;
        const float dy = a.y - b.y;
        const float dz = a.z - b.z;
        const float dw = a.w - b.w;
        float s = dx * dx + dy * dy + dz * dz + dw * dw;

        // Warp tree-reduce sum of squares.
        #pragma unroll
        for (int off = 16; off > 0; off >>= 1)
            s += __shfl_xor_sync(0xffffffffu, s, off);

        if (lane == 0) {
            const float d = desire[row];
            l_des += (double)d;
            if (s > margin_sq) {
                l_cnt += 1u;
                l_inter += (double)d;
            }
        }
    }

    // Block-level reduction across warps (only lane-0 values matter).
    __shared__ double       s_inter[8];
    __shared__ double       s_des[8];
    __shared__ unsigned int s_cnt[8];
    if (lane == 0) {
        s_inter[warp_in_block] = l_inter;
        s_des[warp_in_block]   = l_des;
        s_cnt[warp_in_block]   = l_cnt;
    }
    __syncthreads();

    if (threadIdx.x == 0) {
        double       bi = 0.0, bd = 0.0;
        unsigned int bc = 0u;
        #pragma unroll
        for (int w = 0; w < 8; w++) {
            bi += s_inter[w];
            bd += s_des[w];
            bc += s_cnt[w];
        }
        atomicAdd(&g_inter, bi);
        atomicAdd(&g_desire_sum, bd);
        atomicAdd(&g_count, (unsigned long long)bc);
    }
}

__global__ void fra_final_kernel(float* __restrict__ out) {
    const double inter = g_inter;
    const double uni   = (double)g_count + g_desire_sum - inter;
    out[0] = (float)((inter + 1e-6) / (uni + 1e-6));
}

extern "C" void kernel_launch(void* const* d_in, const int* in_sizes, int n_in,
                              void* d_out, int out_size) {
    const float4* o1     = (const float4*)d_in[0];  // output1 [N,128] fp32
    const float4* o2     = (const float4*)d_in[1];  // output2 [N,128] fp32
    const float*  desire = (const float*)d_in[2];   // desire  [N,1]  fp32
    float*        out    = (float*)d_out;

    const int n_rows = in_sizes[2];  // N = 262144 (desire has N elements)

    fra_zero_kernel<<<1, 1>>>();

    // Persistent grid: 148 SMs x 8 blocks of 256 threads (full occupancy).
    const int threads = 256;
    const int blocks  = 148 * 8;
    fra_main_kernel<<<blocks, threads>>>(o1, o2, desire, n_rows);

    fra_final_kernel<<<1, 1>>>(out);
}